// round 1
// baseline (speedup 1.0000x reference)
#include <cuda_runtime.h>
#include <math.h>

#define NO 50000
#define NR 2000
#define NE 600000
#define D  128
#define NEG_SLOPE 0.2f

// ---------------- scratch (device globals; no allocation allowed) ----------------
__device__ float g_v1[D], g_vd1[D], g_v2[D], g_vd2[D];
__device__ float g_as1[NO], g_as2[NO];
__device__ float g_ad1[NR], g_ad2[NR];
__device__ int   g_counts[NR];
__device__ int   g_rowptr[NR + 1];
__device__ int   g_cursor[NR];
__device__ int   g_ois[NE];
__device__ float g_agg[NR * D];
__device__ float g_r1[NR * D];
__device__ float g_r2[NR * D];

__device__ __forceinline__ float lrelu(float x) { return x > 0.f ? x : NEG_SLOPE * x; }

// ---------------- v = W @ a  (4 tiny matvecs, one block each) ----------------
__global__ void prep_vecs(const float* __restrict__ Ws1, const float* __restrict__ as1,
                          const float* __restrict__ Wd1, const float* __restrict__ ad1,
                          const float* __restrict__ Ws2, const float* __restrict__ as2,
                          const float* __restrict__ Wd2, const float* __restrict__ ad2) {
    int t = threadIdx.x;
    const float *W, *a;
    float* v;
    switch (blockIdx.x) {
        case 0: W = Ws1; a = as1; v = g_v1;  break;
        case 1: W = Wd1; a = ad1; v = g_vd1; break;
        case 2: W = Ws2; a = as2; v = g_v2;  break;
        default: W = Wd2; a = ad2; v = g_vd2; break;
    }
    float s = 0.f;
    #pragma unroll 8
    for (int d = 0; d < D; d++) s += W[t * D + d] * a[d];
    v[t] = s;
}

__global__ void zero_counts() {
    int i = blockIdx.x * blockDim.x + threadIdx.x;
    if (i < NR) g_counts[i] = 0;
}

// ---------------- alpha_s1[o] = x·v1 ; alpha_s2[o] = relu(x)·v2 (warp/row) ----------------
__global__ void alpha_order_kernel(const float* __restrict__ x) {
    int row = blockIdx.x * 8 + (threadIdx.x >> 5);
    if (row >= NO) return;
    int lane = threadIdx.x & 31;
    float4 xv = ((const float4*)x)[row * 32 + lane];
    float4 v1 = ((const float4*)g_v1)[lane];
    float4 v2 = ((const float4*)g_v2)[lane];
    float s1 = xv.x * v1.x + xv.y * v1.y + xv.z * v1.z + xv.w * v1.w;
    float s2 = fmaxf(xv.x, 0.f) * v2.x + fmaxf(xv.y, 0.f) * v2.y +
               fmaxf(xv.z, 0.f) * v2.z + fmaxf(xv.w, 0.f) * v2.w;
    #pragma unroll
    for (int o = 16; o; o >>= 1) {
        s1 += __shfl_down_sync(0xffffffffu, s1, o);
        s2 += __shfl_down_sync(0xffffffffu, s2, o);
    }
    if (lane == 0) { g_as1[row] = s1; g_as2[row] = s2; }
}

// ---------------- generic warp-per-row dot: out[r] = X[r]·v ----------------
__global__ void rowdot_kernel(const float* __restrict__ X, const float* __restrict__ v,
                              float* __restrict__ out, int n) {
    int row = blockIdx.x * 8 + (threadIdx.x >> 5);
    if (row >= n) return;
    int lane = threadIdx.x & 31;
    float4 xv = ((const float4*)X)[row * 32 + lane];
    float4 vv = ((const float4*)v)[lane];
    float s = xv.x * vv.x + xv.y * vv.y + xv.z * vv.z + xv.w * vv.w;
    #pragma unroll
    for (int o = 16; o; o >>= 1) s += __shfl_down_sync(0xffffffffu, s, o);
    if (lane == 0) out[row] = s;
}

// ---------------- CSR build ----------------
__global__ void hist_kernel(const int* __restrict__ ri) {
    __shared__ int sh[NR];
    for (int i = threadIdx.x; i < NR; i += blockDim.x) sh[i] = 0;
    __syncthreads();
    for (int e = blockIdx.x * blockDim.x + threadIdx.x; e < NE; e += gridDim.x * blockDim.x)
        atomicAdd(&sh[ri[e]], 1);
    __syncthreads();
    for (int i = threadIdx.x; i < NR; i += blockDim.x)
        if (sh[i]) atomicAdd(&g_counts[i], sh[i]);
}

__global__ void scan_kernel() {
    __shared__ int bufA[2048], bufB[2048];
    int tid = threadIdx.x;  // 1024
    for (int i = tid; i < 2048; i += 1024) bufA[i] = (i < NR) ? g_counts[i] : 0;
    __syncthreads();
    int* src = bufA; int* dst = bufB;
    for (int off = 1; off < 2048; off <<= 1) {
        for (int i = tid; i < 2048; i += 1024)
            dst[i] = src[i] + (i >= off ? src[i - off] : 0);
        __syncthreads();
        int* t = src; src = dst; dst = t;
    }
    for (int i = tid; i < NR; i += 1024) {
        int excl = (i == 0) ? 0 : src[i - 1];
        g_rowptr[i] = excl;
        g_cursor[i] = excl;
    }
    if (tid == 0) g_rowptr[NR] = src[NR - 1];
}

__global__ void scatter_kernel(const int* __restrict__ oi, const int* __restrict__ ri) {
    for (int e = blockIdx.x * blockDim.x + threadIdx.x; e < NE; e += gridDim.x * blockDim.x) {
        int pos = atomicAdd(&g_cursor[ri[e]], 1);
        g_ois[pos] = oi[e];
    }
}

// ---------------- segment softmax + weighted aggregation (block per rider) ----------------
// out[r] = (sum_e w_e * maybe_relu(x[oi_e])) / (sum_e w_e + 1e-16)
__global__ void agg_kernel(const float* __restrict__ x, const float* __restrict__ asrc,
                           const float* __restrict__ adst, float* __restrict__ out,
                           int relu_x) {
    int r = blockIdx.x;
    int tid = threadIdx.x;          // 256
    int d = tid & (D - 1);
    int sub = tid >> 7;             // 0..1
    int start = g_rowptr[r], end = g_rowptr[r + 1];
    float adr = adst[r];

    __shared__ float red[256];
    __shared__ float swred[2];

    // pass 1: max of asrc over edges (leaky_relu monotone -> only need max of asrc)
    float mx = -3.4e38f;
    for (int j = start + tid; j < end; j += 256)
        mx = fmaxf(mx, asrc[g_ois[j]]);
    red[tid] = mx;
    __syncthreads();
    #pragma unroll
    for (int s2 = 128; s2 > 0; s2 >>= 1) {
        if (tid < s2) red[tid] = fmaxf(red[tid], red[tid + s2]);
        __syncthreads();
    }
    float m = lrelu(red[0] + adr);
    __syncthreads();

    // pass 2: weighted accumulate (2 edges in flight per iteration)
    float acc = 0.f, sumw = 0.f;
    #pragma unroll 4
    for (int j = start + sub; j < end; j += 2) {
        int oi = g_ois[j];
        float w = __expf(lrelu(asrc[oi] + adr) - m);
        float xv = x[oi * D + d];
        if (relu_x) xv = fmaxf(xv, 0.f);
        acc += w * xv;
        sumw += w;
    }
    if (d == 0) swred[sub] = sumw;
    red[tid] = acc;
    __syncthreads();
    if (tid < D) {
        float tot = swred[0] + swred[1];
        float a = red[tid] + red[tid + D];
        out[r * D + tid] = a / (tot + 1e-16f);
    }
}

// ---------------- rider GEMM: out[2000,128] = A[2000,128] @ W[128,128] + b (opt relu) ----------------
__global__ void rider_gemm(const float* __restrict__ Ain, const float* __restrict__ W,
                           const float* __restrict__ bias, float* __restrict__ out,
                           int relu) {
    __shared__ float Ws[32 * 128];
    __shared__ float As[16 * 128];
    int tid = threadIdx.x;  // 128
    int r0 = blockIdx.x * 16;
    for (int i = tid; i < 16 * 128; i += 128) As[i] = Ain[r0 * 128 + i];
    float acc[16];
    #pragma unroll
    for (int i = 0; i < 16; i++) acc[i] = 0.f;
    for (int kk = 0; kk < 4; kk++) {
        __syncthreads();
        for (int i = tid; i < 32 * 128; i += 128) Ws[i] = W[kk * 32 * 128 + i];
        __syncthreads();
        #pragma unroll 8
        for (int k = 0; k < 32; k++) {
            float wv = Ws[k * 128 + tid];
            #pragma unroll
            for (int i = 0; i < 16; i++) acc[i] += As[i * 128 + kk * 32 + k] * wv;
        }
    }
    float bv = bias[tid];
    #pragma unroll
    for (int i = 0; i < 16; i++) {
        float o = acc[i] + bv;
        if (relu) o = fmaxf(o, 0.f);
        out[(r0 + i) * 128 + tid] = o;
    }
}

// ---------------- scoring: out[e] = sigmoid( relu(x[oi])·r2[ri] ), warp per edge ----------------
__global__ void score_kernel(const float* __restrict__ x, const int* __restrict__ oi,
                             const int* __restrict__ ri, const float* __restrict__ r2,
                             float* __restrict__ out) {
    int e = blockIdx.x * 8 + (threadIdx.x >> 5);
    if (e >= NE) return;
    int lane = threadIdx.x & 31;
    int o = oi[e], r = ri[e];
    float4 xv = ((const float4*)x)[o * 32 + lane];
    float4 rv = ((const float4*)r2)[r * 32 + lane];
    float s = fmaxf(xv.x, 0.f) * rv.x + fmaxf(xv.y, 0.f) * rv.y +
              fmaxf(xv.z, 0.f) * rv.z + fmaxf(xv.w, 0.f) * rv.w;
    #pragma unroll
    for (int off = 16; off; off >>= 1) s += __shfl_down_sync(0xffffffffu, s, off);
    if (lane == 0) out[e] = 1.f / (1.f + __expf(-s));
}

// ---------------- launch ----------------
extern "C" void kernel_launch(void* const* d_in, const int* in_sizes, int n_in,
                              void* d_out, int out_size) {
    const float* x_order  = (const float*)d_in[0];
    const float* x_rider  = (const float*)d_in[1];
    const int*   order_idx = (const int*)d_in[2];
    const int*   rider_idx = (const int*)d_in[3];
    const float* Ws1 = (const float*)d_in[4];
    const float* Wd1 = (const float*)d_in[5];
    const float* as1 = (const float*)d_in[6];
    const float* ad1 = (const float*)d_in[7];
    const float* b1  = (const float*)d_in[8];
    const float* Ws2 = (const float*)d_in[9];
    const float* Wd2 = (const float*)d_in[10];
    const float* as2 = (const float*)d_in[11];
    const float* ad2 = (const float*)d_in[12];
    const float* b2  = (const float*)d_in[13];
    float* out = (float*)d_out;

    float *p_vd1, *p_vd2, *p_as1, *p_as2, *p_ad1, *p_ad2, *p_agg, *p_r1, *p_r2;
    cudaGetSymbolAddress((void**)&p_vd1, g_vd1);
    cudaGetSymbolAddress((void**)&p_vd2, g_vd2);
    cudaGetSymbolAddress((void**)&p_as1, g_as1);
    cudaGetSymbolAddress((void**)&p_as2, g_as2);
    cudaGetSymbolAddress((void**)&p_ad1, g_ad1);
    cudaGetSymbolAddress((void**)&p_ad2, g_ad2);
    cudaGetSymbolAddress((void**)&p_agg, g_agg);
    cudaGetSymbolAddress((void**)&p_r1,  g_r1);
    cudaGetSymbolAddress((void**)&p_r2,  g_r2);

    prep_vecs<<<4, 128>>>(Ws1, as1, Wd1, ad1, Ws2, as2, Wd2, ad2);
    zero_counts<<<(NR + 255) / 256, 256>>>();
    alpha_order_kernel<<<NO / 8, 256>>>(x_order);
    rowdot_kernel<<<NR / 8, 256>>>(x_rider, p_vd1, p_ad1, NR);
    hist_kernel<<<240, 256>>>(rider_idx);
    scan_kernel<<<1, 1024>>>();
    scatter_kernel<<<240, 256>>>(order_idx, rider_idx);

    // layer 1: aggregate raw x_order rows, then tiny GEMM + bias + relu
    agg_kernel<<<NR, 256>>>(x_order, p_as1, p_ad1, p_agg, 0);
    rider_gemm<<<NR / 16, 128>>>(p_agg, Ws1, b1, p_r1, 1);

    // layer 2 attention dst logits, aggregate relu(x_order), tiny GEMM + bias
    rowdot_kernel<<<NR / 8, 256>>>(p_r1, p_vd2, p_ad2, NR);
    agg_kernel<<<NR, 256>>>(x_order, p_as2, p_ad2, p_agg, 1);
    rider_gemm<<<NR / 16, 128>>>(p_agg, Ws2, b2, p_r2, 0);

    // per-edge scoring
    score_kernel<<<NE / 8, 256>>>(x_order, order_idx, rider_idx, p_r2, out);
}

// round 3
// speedup vs baseline: 1.4153x; 1.4153x over previous
#include <cuda_runtime.h>
#include <cuda_fp16.h>
#include <math.h>

#define NO 50000
#define NR 2000
#define NE 600000
#define D  128
#define NEG_SLOPE 0.2f

// ---------------- scratch (device globals; no allocation allowed) ----------------
__device__ float  g_v1[D], g_vd1[D], g_v2[D], g_vd2[D];
__device__ float2 g_as12[NO];          // (alpha_s layer1, alpha_s layer2) per order
__device__ float  g_ad1[NR], g_ad2[NR];
__device__ float  g_mx2[NR];           // per-rider max of as2 (computed in agg1 pass1)
__device__ int    g_counts[NR];
__device__ int    g_rowptr[NR + 1];
__device__ int    g_cursor[NR];
__device__ int    g_ois[NE];
__device__ int    g_eids[NE];
__device__ __half g_xh[NO * D];        // fp16 copy of x_order (12.8 MB, L2-resident)
__device__ float  g_agg[NR * D];
__device__ float  g_r1[NR * D];
__device__ float  g_r2[NR * D];

__device__ __forceinline__ float lrelu(float x) { return x > 0.f ? x : NEG_SLOPE * x; }

// ---------------- v = W @ a  (4 tiny matvecs, one block each) ----------------
__global__ void prep_vecs(const float* __restrict__ Ws1, const float* __restrict__ as1,
                          const float* __restrict__ Wd1, const float* __restrict__ ad1,
                          const float* __restrict__ Ws2, const float* __restrict__ as2,
                          const float* __restrict__ Wd2, const float* __restrict__ ad2) {
    int t = threadIdx.x;
    const float *W, *a;
    float* v;
    switch (blockIdx.x) {
        case 0: W = Ws1; a = as1; v = g_v1;  break;
        case 1: W = Wd1; a = ad1; v = g_vd1; break;
        case 2: W = Ws2; a = as2; v = g_v2;  break;
        default: W = Wd2; a = ad2; v = g_vd2; break;
    }
    float s = 0.f;
    #pragma unroll 8
    for (int d = 0; d < D; d++) s += W[t * D + d] * a[d];
    v[t] = s;
}

__global__ void zero_counts() {
    int i = blockIdx.x * blockDim.x + threadIdx.x;
    if (i < NR) g_counts[i] = 0;
}

// ---------------- convert x_order->fp16 + alpha_s1 = x.v1, alpha_s2 = relu(x).v2 ----------------
__global__ void convert_alpha(const float* __restrict__ x) {
    int row = blockIdx.x * 8 + (threadIdx.x >> 5);
    if (row >= NO) return;
    int lane = threadIdx.x & 31;
    float4 xv = ((const float4*)x)[row * 32 + lane];
    // fp16 cache
    __half2 h01 = __floats2half2_rn(xv.x, xv.y);
    __half2 h23 = __floats2half2_rn(xv.z, xv.w);
    uint2 u;
    *reinterpret_cast<__half2*>(&u.x) = h01;
    *reinterpret_cast<__half2*>(&u.y) = h23;
    reinterpret_cast<uint2*>(g_xh)[row * 32 + lane] = u;
    // alpha logits
    float4 v1 = ((const float4*)g_v1)[lane];
    float4 v2 = ((const float4*)g_v2)[lane];
    float s1 = xv.x * v1.x + xv.y * v1.y + xv.z * v1.z + xv.w * v1.w;
    float s2 = fmaxf(xv.x, 0.f) * v2.x + fmaxf(xv.y, 0.f) * v2.y +
               fmaxf(xv.z, 0.f) * v2.z + fmaxf(xv.w, 0.f) * v2.w;
    #pragma unroll
    for (int o = 16; o; o >>= 1) {
        s1 += __shfl_down_sync(0xffffffffu, s1, o);
        s2 += __shfl_down_sync(0xffffffffu, s2, o);
    }
    if (lane == 0) g_as12[row] = make_float2(s1, s2);
}

// ---------------- generic warp-per-row dot: out[r] = X[r].v ----------------
__global__ void rowdot_kernel(const float* __restrict__ X, const float* __restrict__ v,
                              float* __restrict__ out, int n) {
    int row = blockIdx.x * 8 + (threadIdx.x >> 5);
    if (row >= n) return;
    int lane = threadIdx.x & 31;
    float4 xv = ((const float4*)X)[row * 32 + lane];
    float4 vv = ((const float4*)v)[lane];
    float s = xv.x * vv.x + xv.y * vv.y + xv.z * vv.z + xv.w * vv.w;
    #pragma unroll
    for (int o = 16; o; o >>= 1) s += __shfl_down_sync(0xffffffffu, s, o);
    if (lane == 0) out[row] = s;
}

// ---------------- CSR build ----------------
__global__ void hist_kernel(const int* __restrict__ ri) {
    __shared__ int sh[NR];
    for (int i = threadIdx.x; i < NR; i += blockDim.x) sh[i] = 0;
    __syncthreads();
    for (int e = blockIdx.x * blockDim.x + threadIdx.x; e < NE; e += gridDim.x * blockDim.x)
        atomicAdd(&sh[ri[e]], 1);
    __syncthreads();
    for (int i = threadIdx.x; i < NR; i += blockDim.x)
        if (sh[i]) atomicAdd(&g_counts[i], sh[i]);
}

__global__ void scan_kernel() {
    __shared__ int bufA[2048], bufB[2048];
    int tid = threadIdx.x;  // 1024
    for (int i = tid; i < 2048; i += 1024) bufA[i] = (i < NR) ? g_counts[i] : 0;
    __syncthreads();
    int* src = bufA; int* dst = bufB;
    for (int off = 1; off < 2048; off <<= 1) {
        for (int i = tid; i < 2048; i += 1024)
            dst[i] = src[i] + (i >= off ? src[i - off] : 0);
        __syncthreads();
        int* t = src; src = dst; dst = t;
    }
    for (int i = tid; i < NR; i += 1024) {
        int excl = (i == 0) ? 0 : src[i - 1];
        g_rowptr[i] = excl;
        g_cursor[i] = excl;
    }
    if (tid == 0) g_rowptr[NR] = src[NR - 1];
}

__global__ void scatter_kernel(const int* __restrict__ oi, const int* __restrict__ ri) {
    for (int e = blockIdx.x * blockDim.x + threadIdx.x; e < NE; e += gridDim.x * blockDim.x) {
        int pos = atomicAdd(&g_cursor[ri[e]], 1);
        g_ois[pos] = oi[e];
        g_eids[pos] = e;
    }
}

// ---------------- layer-1 aggregation (also records layer-2 max) ----------------
// block = 256 threads = 8 warps, one rider per block; warp-per-edge in main pass
__global__ void agg1_kernel(const float* __restrict__ adst) {
    int r = blockIdx.x;
    int tid = threadIdx.x;
    int warp = tid >> 5, lane = tid & 31;
    int start = g_rowptr[r], end = g_rowptr[r + 1];
    float adr = adst[r];

    // pass 1: max of as1 and as2 over this rider's edges
    float mx1 = -3.4e38f, mx2 = -3.4e38f;
    for (int j = start + tid; j < end; j += 256) {
        float2 a = g_as12[g_ois[j]];
        mx1 = fmaxf(mx1, a.x);
        mx2 = fmaxf(mx2, a.y);
    }
    #pragma unroll
    for (int o = 16; o; o >>= 1) {
        mx1 = fmaxf(mx1, __shfl_xor_sync(0xffffffffu, mx1, o));
        mx2 = fmaxf(mx2, __shfl_xor_sync(0xffffffffu, mx2, o));
    }
    __shared__ float sm1[8], sm2[8];
    __shared__ float s_m1;
    if (lane == 0) { sm1[warp] = mx1; sm2[warp] = mx2; }
    __syncthreads();
    if (tid == 0) {
        float a = -3.4e38f, b = -3.4e38f;
        #pragma unroll
        for (int w = 0; w < 8; w++) { a = fmaxf(a, sm1[w]); b = fmaxf(b, sm2[w]); }
        s_m1 = lrelu(a + adr);
        g_mx2[r] = b;
    }
    __syncthreads();
    float m1 = s_m1;

    // pass 2: warp-per-edge weighted accumulation of fp16 rows
    float4 acc = make_float4(0.f, 0.f, 0.f, 0.f);
    float sumw = 0.f;
    const uint2* xh = reinterpret_cast<const uint2*>(g_xh);
    for (int j = start + warp; j < end; j += 8) {
        int oi = g_ois[j];
        float as = g_as12[oi].x;
        float w = __expf(lrelu(as + adr) - m1);
        uint2 u = xh[oi * 32 + lane];
        float2 f01 = __half22float2(*reinterpret_cast<__half2*>(&u.x));
        float2 f23 = __half22float2(*reinterpret_cast<__half2*>(&u.y));
        acc.x += w * f01.x; acc.y += w * f01.y;
        acc.z += w * f23.x; acc.w += w * f23.y;
        sumw += w;
    }
    __shared__ float4 s_acc[8][32];
    __shared__ float s_w[8];
    s_acc[warp][lane] = acc;
    if (lane == 0) s_w[warp] = sumw;
    __syncthreads();
    if (tid < 128) {
        float tot = 0.f;
        #pragma unroll
        for (int w = 0; w < 8; w++) tot += s_w[w];
        const float* sf = reinterpret_cast<const float*>(s_acc);
        float a = 0.f;
        #pragma unroll
        for (int w = 0; w < 8; w++) a += sf[w * 128 + tid];
        g_agg[r * 128 + tid] = a / (tot + 1e-16f);
    }
}

// ---------------- layer-2 aggregation: single pass (max reused), relu(x) inline ----------------
__global__ void agg2_kernel(const float* __restrict__ adst) {
    int r = blockIdx.x;
    int tid = threadIdx.x;
    int warp = tid >> 5, lane = tid & 31;
    int start = g_rowptr[r], end = g_rowptr[r + 1];
    float adr = adst[r];
    float m2 = lrelu(g_mx2[r] + adr);

    float4 acc = make_float4(0.f, 0.f, 0.f, 0.f);
    float sumw = 0.f;
    const uint2* xh = reinterpret_cast<const uint2*>(g_xh);
    for (int j = start + warp; j < end; j += 8) {
        int oi = g_ois[j];
        float as = g_as12[oi].y;
        float w = __expf(lrelu(as + adr) - m2);
        uint2 u = xh[oi * 32 + lane];
        float2 f01 = __half22float2(*reinterpret_cast<__half2*>(&u.x));
        float2 f23 = __half22float2(*reinterpret_cast<__half2*>(&u.y));
        acc.x += w * fmaxf(f01.x, 0.f); acc.y += w * fmaxf(f01.y, 0.f);
        acc.z += w * fmaxf(f23.x, 0.f); acc.w += w * fmaxf(f23.y, 0.f);
        sumw += w;
    }
    __shared__ float4 s_acc[8][32];
    __shared__ float s_w[8];
    s_acc[warp][lane] = acc;
    if (lane == 0) s_w[warp] = sumw;
    __syncthreads();
    if (tid < 128) {
        float tot = 0.f;
        #pragma unroll
        for (int w = 0; w < 8; w++) tot += s_w[w];
        const float* sf = reinterpret_cast<const float*>(s_acc);
        float a = 0.f;
        #pragma unroll
        for (int w = 0; w < 8; w++) a += sf[w * 128 + tid];
        g_agg[r * 128 + tid] = a / (tot + 1e-16f);
    }
}

// ---------------- rider GEMM: out[2000,128] = A @ W + b (opt relu) ----------------
__global__ void rider_gemm(const float* __restrict__ Ain, const float* __restrict__ W,
                           const float* __restrict__ bias, float* __restrict__ out,
                           int relu) {
    __shared__ float Ws[32 * 128];
    __shared__ float As[16 * 128];
    int tid = threadIdx.x;  // 128
    int r0 = blockIdx.x * 16;
    for (int i = tid; i < 16 * 128; i += 128) As[i] = Ain[r0 * 128 + i];
    float acc[16];
    #pragma unroll
    for (int i = 0; i < 16; i++) acc[i] = 0.f;
    for (int kk = 0; kk < 4; kk++) {
        __syncthreads();
        for (int i = tid; i < 32 * 128; i += 128) Ws[i] = W[kk * 32 * 128 + i];
        __syncthreads();
        #pragma unroll 8
        for (int k = 0; k < 32; k++) {
            float wv = Ws[k * 128 + tid];
            #pragma unroll
            for (int i = 0; i < 16; i++) acc[i] += As[i * 128 + kk * 32 + k] * wv;
        }
    }
    float bv = bias[tid];
    #pragma unroll
    for (int i = 0; i < 16; i++) {
        float o = acc[i] + bv;
        if (relu) o = fmaxf(o, 0.f);
        out[(r0 + i) * 128 + tid] = o;
    }
}

// ---------------- CSR-ordered scoring: block per rider, r2 row in registers ----------------
__global__ void score_csr(const float* __restrict__ r2, float* __restrict__ out) {
    int r = blockIdx.x;
    int warp = threadIdx.x >> 5, lane = threadIdx.x & 31;
    int start = g_rowptr[r], end = g_rowptr[r + 1];
    float4 rv = ((const float4*)(r2 + r * 128))[lane];
    const uint2* xh = reinterpret_cast<const uint2*>(g_xh);
    for (int j = start + warp; j < end; j += 8) {
        int oi = g_ois[j];
        int eid = g_eids[j];
        uint2 u = xh[oi * 32 + lane];
        float2 f01 = __half22float2(*reinterpret_cast<__half2*>(&u.x));
        float2 f23 = __half22float2(*reinterpret_cast<__half2*>(&u.y));
        float s = fmaxf(f01.x, 0.f) * rv.x + fmaxf(f01.y, 0.f) * rv.y +
                  fmaxf(f23.x, 0.f) * rv.z + fmaxf(f23.y, 0.f) * rv.w;
        #pragma unroll
        for (int o = 16; o; o >>= 1) s += __shfl_down_sync(0xffffffffu, s, o);
        if (lane == 0) out[eid] = 1.f / (1.f + __expf(-s));
    }
}

// ---------------- launch ----------------
extern "C" void kernel_launch(void* const* d_in, const int* in_sizes, int n_in,
                              void* d_out, int out_size) {
    const float* x_order   = (const float*)d_in[0];
    const float* x_rider   = (const float*)d_in[1];
    const int*   order_idx = (const int*)d_in[2];
    const int*   rider_idx = (const int*)d_in[3];
    const float* Ws1 = (const float*)d_in[4];
    const float* Wd1 = (const float*)d_in[5];
    const float* as1 = (const float*)d_in[6];
    const float* ad1 = (const float*)d_in[7];
    const float* b1  = (const float*)d_in[8];
    const float* Ws2 = (const float*)d_in[9];
    const float* Wd2 = (const float*)d_in[10];
    const float* as2 = (const float*)d_in[11];
    const float* ad2 = (const float*)d_in[12];
    const float* b2  = (const float*)d_in[13];
    float* out = (float*)d_out;

    float *p_vd1, *p_vd2, *p_ad1, *p_ad2, *p_agg, *p_r1, *p_r2;
    cudaGetSymbolAddress((void**)&p_vd1, g_vd1);
    cudaGetSymbolAddress((void**)&p_vd2, g_vd2);
    cudaGetSymbolAddress((void**)&p_ad1, g_ad1);
    cudaGetSymbolAddress((void**)&p_ad2, g_ad2);
    cudaGetSymbolAddress((void**)&p_agg, g_agg);
    cudaGetSymbolAddress((void**)&p_r1,  g_r1);
    cudaGetSymbolAddress((void**)&p_r2,  g_r2);

    prep_vecs<<<4, 128>>>(Ws1, as1, Wd1, ad1, Ws2, as2, Wd2, ad2);
    zero_counts<<<(NR + 255) / 256, 256>>>();
    convert_alpha<<<NO / 8, 256>>>(x_order);
    rowdot_kernel<<<NR / 8, 256>>>(x_rider, p_vd1, p_ad1, NR);
    hist_kernel<<<240, 256>>>(rider_idx);
    scan_kernel<<<1, 1024>>>();
    scatter_kernel<<<240, 256>>>(order_idx, rider_idx);

    // layer 1
    agg1_kernel<<<NR, 256>>>(p_ad1);
    rider_gemm<<<NR / 16, 128>>>(p_agg, Ws1, b1, p_r1, 1);

    // layer 2
    rowdot_kernel<<<NR / 8, 256>>>(p_r1, p_vd2, p_ad2, NR);
    agg2_kernel<<<NR, 256>>>(p_ad2);
    rider_gemm<<<NR / 16, 128>>>(p_agg, Ws2, b2, p_r2, 0);

    // per-edge scoring in CSR order
    score_csr<<<NR, 256>>>(p_r2, out);
}

// round 4
// speedup vs baseline: 1.4828x; 1.0477x over previous
#include <cuda_runtime.h>
#include <cuda_fp16.h>
#include <math.h>

#define NO 50000
#define NR 2000
#define NE 600000
#define D  128
#define NEG_SLOPE 0.2f

// ---------------- scratch (device globals; no allocation allowed) ----------------
__device__ float  g_v1[D], g_vd1[D], g_v2[D], g_vd2[D];
__device__ float2 g_as12[NO];          // (alpha_s layer1, alpha_s layer2) per order
__device__ float  g_ad2[NR];
__device__ int    g_counts[NR];
__device__ int    g_rowptr[NR + 1];
__device__ int    g_cursor[NR];
__device__ int2   g_edge[NE];          // (order_idx, edge_id) in CSR order
__device__ __half g_xh[NO * D];        // fp16 copy of x_order (12.8 MB, L2-resident)

__device__ __forceinline__ float lrelu(float x) { return x > 0.f ? x : NEG_SLOPE * x; }

// ---------------- prep: 4 matvecs v = W@a  + zero counts ----------------
__global__ void prep_kernel(const float* __restrict__ Ws1, const float* __restrict__ as1,
                            const float* __restrict__ Wd1, const float* __restrict__ ad1,
                            const float* __restrict__ Ws2, const float* __restrict__ as2,
                            const float* __restrict__ Wd2, const float* __restrict__ ad2) {
    int t = threadIdx.x;  // 128
    if (blockIdx.x == 4) {
        for (int i = t; i < NR; i += 128) g_counts[i] = 0;
        return;
    }
    const float *W, *a;
    float* v;
    switch (blockIdx.x) {
        case 0: W = Ws1; a = as1; v = g_v1;  break;
        case 1: W = Wd1; a = ad1; v = g_vd1; break;
        case 2: W = Ws2; a = as2; v = g_v2;  break;
        default: W = Wd2; a = ad2; v = g_vd2; break;
    }
    float s = 0.f;
    #pragma unroll 8
    for (int d = 0; d < D; d++) s += W[t * D + d] * a[d];
    v[t] = s;
}

// ---------------- convert x->fp16, alpha logits; tail blocks: histogram ----------------
#define CONV_BLKS (NO / 8)   // 6250
#define HIST_BLKS 60
#define HIST_CHUNK (NE / HIST_BLKS)  // 10000
__global__ void convert_hist_kernel(const float* __restrict__ x, const int* __restrict__ ri) {
    __shared__ int sh[NR];
    if (blockIdx.x < CONV_BLKS) {
        int row = blockIdx.x * 8 + (threadIdx.x >> 5);
        int lane = threadIdx.x & 31;
        float4 xv = ((const float4*)x)[row * 32 + lane];
        __half2 h01 = __floats2half2_rn(xv.x, xv.y);
        __half2 h23 = __floats2half2_rn(xv.z, xv.w);
        uint2 u;
        *reinterpret_cast<__half2*>(&u.x) = h01;
        *reinterpret_cast<__half2*>(&u.y) = h23;
        reinterpret_cast<uint2*>(g_xh)[row * 32 + lane] = u;
        float4 v1 = ((const float4*)g_v1)[lane];
        float4 v2 = ((const float4*)g_v2)[lane];
        float s1 = xv.x * v1.x + xv.y * v1.y + xv.z * v1.z + xv.w * v1.w;
        float s2 = fmaxf(xv.x, 0.f) * v2.x + fmaxf(xv.y, 0.f) * v2.y +
                   fmaxf(xv.z, 0.f) * v2.z + fmaxf(xv.w, 0.f) * v2.w;
        #pragma unroll
        for (int o = 16; o; o >>= 1) {
            s1 += __shfl_down_sync(0xffffffffu, s1, o);
            s2 += __shfl_down_sync(0xffffffffu, s2, o);
        }
        if (lane == 0) g_as12[row] = make_float2(s1, s2);
    } else {
        int b = blockIdx.x - CONV_BLKS;
        int lo = b * HIST_CHUNK, hi = lo + HIST_CHUNK;
        for (int i = threadIdx.x; i < NR; i += blockDim.x) sh[i] = 0;
        __syncthreads();
        for (int e = lo + threadIdx.x; e < hi; e += blockDim.x)
            atomicAdd(&sh[ri[e]], 1);
        __syncthreads();
        for (int i = threadIdx.x; i < NR; i += blockDim.x)
            if (sh[i]) atomicAdd(&g_counts[i], sh[i]);
    }
}

// ---------------- scan: rowptr + cursor init ----------------
__global__ void scan_kernel() {
    __shared__ int bufA[2048], bufB[2048];
    int tid = threadIdx.x;  // 1024
    for (int i = tid; i < 2048; i += 1024) bufA[i] = (i < NR) ? g_counts[i] : 0;
    __syncthreads();
    int* src = bufA; int* dst = bufB;
    for (int off = 1; off < 2048; off <<= 1) {
        for (int i = tid; i < 2048; i += 1024)
            dst[i] = src[i] + (i >= off ? src[i - off] : 0);
        __syncthreads();
        int* t = src; src = dst; dst = t;
    }
    for (int i = tid; i < NR; i += 1024) {
        int excl = (i == 0) ? 0 : src[i - 1];
        g_rowptr[i] = excl;
        g_cursor[i] = excl;
    }
    if (tid == 0) g_rowptr[NR] = src[NR - 1];
}

// ---------------- scatter: two-phase smem counting (few global atomics) ----------------
#define SCAT_BLKS 60
#define SCAT_CHUNK (NE / SCAT_BLKS)  // 10000
__global__ void scatter_kernel(const int* __restrict__ oi, const int* __restrict__ ri) {
    __shared__ int cnt[NR], base[NR];
    int tid = threadIdx.x;  // 512
    int lo = blockIdx.x * SCAT_CHUNK, hi = lo + SCAT_CHUNK;
    for (int i = tid; i < NR; i += 512) cnt[i] = 0;
    __syncthreads();
    for (int e = lo + tid; e < hi; e += 512) atomicAdd(&cnt[ri[e]], 1);
    __syncthreads();
    for (int i = tid; i < NR; i += 512) {
        int c = cnt[i];
        base[i] = c ? atomicAdd(&g_cursor[i], c) : 0;
        cnt[i] = 0;
    }
    __syncthreads();
    for (int e = lo + tid; e < hi; e += 512) {
        int rr = ri[e];
        int pos = base[rr] + atomicAdd(&cnt[rr], 1);
        g_edge[pos] = make_int2(oi[e], e);
    }
}

// ---------------- kernel A: layer-1 agg + matvec(Ws1)+relu+dot(vd2) -> ad2 ----------------
// 8 riders per block, 1024 threads (32 warps). Ws1 fp32 in 64KB dynamic smem.
__global__ void __launch_bounds__(1024) kernelA(const float* __restrict__ xr,
                                                const float* __restrict__ Ws1,
                                                const float* __restrict__ b1) {
    extern __shared__ float Wsm[];               // 128*128 fp32
    __shared__ float4 s_acc[32][32];             // per-warp partials
    __shared__ float  s_w[32];
    __shared__ float  s_agg[128];
    __shared__ float  s_part[8][128];
    __shared__ float  s_red[128];
    __shared__ float  s_ad1[8];
    __shared__ float  s_tot;

    int tid = threadIdx.x, warp = tid >> 5, lane = tid & 31;
    for (int i = tid; i < 128 * 128; i += 1024) Wsm[i] = Ws1[i];

    int r0 = blockIdx.x * 8;
    if (warp < 8) {   // ad1 for the 8 riders
        int r = r0 + warp;
        float4 xv = ((const float4*)xr)[r * 32 + lane];
        float4 vv = ((const float4*)g_vd1)[lane];
        float s = xv.x * vv.x + xv.y * vv.y + xv.z * vv.z + xv.w * vv.w;
        #pragma unroll
        for (int o = 16; o; o >>= 1) s += __shfl_down_sync(0xffffffffu, s, o);
        if (lane == 0) s_ad1[warp] = s;
    }
    float b1t = 0.f, vd2t = 0.f;
    if (tid < 128) { b1t = b1[tid]; vd2t = g_vd2[tid]; }
    __syncthreads();

    const uint2* xh = reinterpret_cast<const uint2*>(g_xh);
    for (int ri = 0; ri < 8; ri++) {
        int r = r0 + ri;
        int start = g_rowptr[r], end = g_rowptr[r + 1];
        float adr = s_ad1[ri];
        float4 acc = make_float4(0.f, 0.f, 0.f, 0.f);
        float sumw = 0.f;
        // 2-edge pipelined gather
        for (int j = start + warp; j < end; j += 64) {
            int j2 = j + 32;
            bool h2 = j2 < end;
            int o1 = g_edge[j].x;
            int o2 = h2 ? g_edge[j2].x : o1;
            float a1 = g_as12[o1].x;
            float a2 = g_as12[o2].x;
            uint2 u1 = xh[o1 * 32 + lane];
            uint2 u2 = xh[o2 * 32 + lane];
            float w1 = __expf(lrelu(a1 + adr));
            float2 f01 = __half22float2(*reinterpret_cast<__half2*>(&u1.x));
            float2 f23 = __half22float2(*reinterpret_cast<__half2*>(&u1.y));
            acc.x += w1 * f01.x; acc.y += w1 * f01.y;
            acc.z += w1 * f23.x; acc.w += w1 * f23.y;
            sumw += w1;
            if (h2) {
                float w2 = __expf(lrelu(a2 + adr));
                float2 g01 = __half22float2(*reinterpret_cast<__half2*>(&u2.x));
                float2 g23 = __half22float2(*reinterpret_cast<__half2*>(&u2.y));
                acc.x += w2 * g01.x; acc.y += w2 * g01.y;
                acc.z += w2 * g23.x; acc.w += w2 * g23.y;
                sumw += w2;
            }
        }
        s_acc[warp][lane] = acc;
        if (lane == 0) s_w[warp] = sumw;
        __syncthreads();
        if (warp == 0) {
            float v = s_w[lane];
            #pragma unroll
            for (int o = 16; o; o >>= 1) v += __shfl_down_sync(0xffffffffu, v, o);
            if (lane == 0) s_tot = v;
        }
        __syncthreads();
        if (tid < 128) {
            const float* sf = reinterpret_cast<const float*>(s_acc);
            float a = 0.f;
            #pragma unroll
            for (int w = 0; w < 32; w++) a += sf[w * 128 + tid];
            s_agg[tid] = a / (s_tot + 1e-16f);
        }
        __syncthreads();
        // matvec: 8 k-slices of 16
        {
            int d = tid & 127, slice = tid >> 7;
            float o = 0.f;
            int k0 = slice * 16;
            #pragma unroll
            for (int k = 0; k < 16; k++) o += s_agg[k0 + k] * Wsm[(k0 + k) * 128 + d];
            s_part[slice][d] = o;
        }
        __syncthreads();
        if (tid < 128) {
            float o = 0.f;
            #pragma unroll
            for (int s = 0; s < 8; s++) o += s_part[s][tid];
            o = fmaxf(o + b1t, 0.f);
            s_red[tid] = o * vd2t;
        }
        __syncthreads();
        if (tid < 32) {
            float v = s_red[tid] + s_red[tid + 32] + s_red[tid + 64] + s_red[tid + 96];
            #pragma unroll
            for (int o = 16; o; o >>= 1) v += __shfl_down_sync(0xffffffffu, v, o);
            if (tid == 0) g_ad2[r] = v;
        }
        __syncthreads();
    }
}

// ---------------- kernel B: layer-2 agg + matvec(Ws2)+b2 -> r2 -> score edges ----------------
__global__ void __launch_bounds__(1024) kernelB(const float* __restrict__ Ws2,
                                                const float* __restrict__ b2,
                                                float* __restrict__ out) {
    extern __shared__ float Wsm[];               // 128*128 fp32
    __shared__ float4 s_acc[32][32];
    __shared__ float  s_w[32];
    __shared__ float  s_agg[128];
    __shared__ float  s_part[8][128];
    __shared__ __align__(16) float s_r2[128];
    __shared__ float  s_tot;

    int tid = threadIdx.x, warp = tid >> 5, lane = tid & 31;
    for (int i = tid; i < 128 * 128; i += 1024) Wsm[i] = Ws2[i];
    float b2t = 0.f;
    if (tid < 128) b2t = b2[tid];
    __syncthreads();

    const uint2* xh = reinterpret_cast<const uint2*>(g_xh);
    int r0 = blockIdx.x * 8;
    for (int ri = 0; ri < 8; ri++) {
        int r = r0 + ri;
        int start = g_rowptr[r], end = g_rowptr[r + 1];
        float adr = g_ad2[r];
        float4 acc = make_float4(0.f, 0.f, 0.f, 0.f);
        float sumw = 0.f;
        for (int j = start + warp; j < end; j += 64) {
            int j2 = j + 32;
            bool h2 = j2 < end;
            int o1 = g_edge[j].x;
            int o2 = h2 ? g_edge[j2].x : o1;
            float a1 = g_as12[o1].y;
            float a2 = g_as12[o2].y;
            uint2 u1 = xh[o1 * 32 + lane];
            uint2 u2 = xh[o2 * 32 + lane];
            float w1 = __expf(lrelu(a1 + adr));
            float2 f01 = __half22float2(*reinterpret_cast<__half2*>(&u1.x));
            float2 f23 = __half22float2(*reinterpret_cast<__half2*>(&u1.y));
            acc.x += w1 * fmaxf(f01.x, 0.f); acc.y += w1 * fmaxf(f01.y, 0.f);
            acc.z += w1 * fmaxf(f23.x, 0.f); acc.w += w1 * fmaxf(f23.y, 0.f);
            sumw += w1;
            if (h2) {
                float w2 = __expf(lrelu(a2 + adr));
                float2 g01 = __half22float2(*reinterpret_cast<__half2*>(&u2.x));
                float2 g23 = __half22float2(*reinterpret_cast<__half2*>(&u2.y));
                acc.x += w2 * fmaxf(g01.x, 0.f); acc.y += w2 * fmaxf(g01.y, 0.f);
                acc.z += w2 * fmaxf(g23.x, 0.f); acc.w += w2 * fmaxf(g23.y, 0.f);
                sumw += w2;
            }
        }
        s_acc[warp][lane] = acc;
        if (lane == 0) s_w[warp] = sumw;
        __syncthreads();
        if (warp == 0) {
            float v = s_w[lane];
            #pragma unroll
            for (int o = 16; o; o >>= 1) v += __shfl_down_sync(0xffffffffu, v, o);
            if (lane == 0) s_tot = v;
        }
        __syncthreads();
        if (tid < 128) {
            const float* sf = reinterpret_cast<const float*>(s_acc);
            float a = 0.f;
            #pragma unroll
            for (int w = 0; w < 32; w++) a += sf[w * 128 + tid];
            s_agg[tid] = a / (s_tot + 1e-16f);
        }
        __syncthreads();
        {
            int d = tid & 127, slice = tid >> 7;
            float o = 0.f;
            int k0 = slice * 16;
            #pragma unroll
            for (int k = 0; k < 16; k++) o += s_agg[k0 + k] * Wsm[(k0 + k) * 128 + d];
            s_part[slice][d] = o;
        }
        __syncthreads();
        if (tid < 128) {
            float o = 0.f;
            #pragma unroll
            for (int s = 0; s < 8; s++) o += s_part[s][tid];
            s_r2[tid] = o + b2t;
        }
        __syncthreads();
        // score this rider's edges; r2 row per-lane in registers
        float4 rv = ((const float4*)s_r2)[lane];
        for (int j = start + warp; j < end; j += 32) {
            int2 oe = g_edge[j];
            uint2 u = xh[oe.x * 32 + lane];
            float2 f01 = __half22float2(*reinterpret_cast<__half2*>(&u.x));
            float2 f23 = __half22float2(*reinterpret_cast<__half2*>(&u.y));
            float s = fmaxf(f01.x, 0.f) * rv.x + fmaxf(f01.y, 0.f) * rv.y +
                      fmaxf(f23.x, 0.f) * rv.z + fmaxf(f23.y, 0.f) * rv.w;
            #pragma unroll
            for (int o = 16; o; o >>= 1) s += __shfl_down_sync(0xffffffffu, s, o);
            if (lane == 0) out[oe.y] = 1.f / (1.f + __expf(-s));
        }
        __syncthreads();
    }
}

// ---------------- launch ----------------
extern "C" void kernel_launch(void* const* d_in, const int* in_sizes, int n_in,
                              void* d_out, int out_size) {
    const float* x_order   = (const float*)d_in[0];
    const float* x_rider   = (const float*)d_in[1];
    const int*   order_idx = (const int*)d_in[2];
    const int*   rider_idx = (const int*)d_in[3];
    const float* Ws1 = (const float*)d_in[4];
    const float* Wd1 = (const float*)d_in[5];
    const float* as1 = (const float*)d_in[6];
    const float* ad1 = (const float*)d_in[7];
    const float* b1  = (const float*)d_in[8];
    const float* Ws2 = (const float*)d_in[9];
    const float* Wd2 = (const float*)d_in[10];
    const float* as2 = (const float*)d_in[11];
    const float* ad2 = (const float*)d_in[12];
    const float* b2  = (const float*)d_in[13];
    float* out = (float*)d_out;

    const int WSMEM = 128 * 128 * sizeof(float);  // 64KB
    cudaFuncSetAttribute(kernelA, cudaFuncAttributeMaxDynamicSharedMemorySize, WSMEM);
    cudaFuncSetAttribute(kernelB, cudaFuncAttributeMaxDynamicSharedMemorySize, WSMEM);

    prep_kernel<<<5, 128>>>(Ws1, as1, Wd1, ad1, Ws2, as2, Wd2, ad2);
    convert_hist_kernel<<<CONV_BLKS + HIST_BLKS, 256>>>(x_order, rider_idx);
    scan_kernel<<<1, 1024>>>();
    scatter_kernel<<<SCAT_BLKS, 512>>>(order_idx, rider_idx);
    kernelA<<<NR / 8, 1024, WSMEM>>>(x_rider, Ws1, b1);
    kernelB<<<NR / 8, 1024, WSMEM>>>(Ws2, b2, out);
}

// round 6
// speedup vs baseline: 1.6649x; 1.1228x over previous
#include <cuda_runtime.h>
#include <cuda_fp16.h>
#include <math.h>

#define NO 50000
#define NR 2000
#define NE 600000
#define D  128
#define NEG_SLOPE 0.2f

// ---------------- scratch ----------------
__device__ float  g_v1[D], g_v2[D], g_vd2[D];
__device__ float  g_ad1[NR], g_ad2[NR];
__device__ float2 g_as12[NO];
__device__ int    g_counts[NR];
__device__ int    g_rowptr[NR + 1];
__device__ int    g_cursor[NR];
__device__ int    g_done;
__device__ int2   g_edge[NE];          // (order_idx, edge_id) CSR order
__device__ __half g_xh[NO * D];        // fp16 x_order cache (12.8MB, L2-resident)
__device__ float  g_agg[NR * D];
__device__ float  g_r2[NR * D];

__device__ __forceinline__ float lrelu(float x) { return x > 0.f ? x : NEG_SLOPE * x; }

// ---------------- prep: v-vectors, ad1 rowdots, zero counters ----------------
// blocks 0..249: vd1 (recomputed in smem) + ad1 for 8 riders each
// block 250: v1 ; 251: v2 ; 252: vd2 ; 253: zero counts + done
__global__ void prep_kernel(const float* __restrict__ xr,
                            const float* __restrict__ Ws1, const float* __restrict__ as1v,
                            const float* __restrict__ Wd1, const float* __restrict__ ad1v,
                            const float* __restrict__ Ws2, const float* __restrict__ as2v,
                            const float* __restrict__ Wd2, const float* __restrict__ ad2v) {
    int b = blockIdx.x, t = threadIdx.x;  // 256 threads
    if (b < 250) {
        __shared__ __align__(16) float vd1[128];
        if (t < 128) {
            float s = 0.f;
            #pragma unroll 8
            for (int d = 0; d < 128; d++) s += Wd1[t * 128 + d] * ad1v[d];
            vd1[t] = s;
        }
        __syncthreads();
        int warp = t >> 5, lane = t & 31;
        int r = b * 8 + warp;
        float4 xv = ((const float4*)xr)[r * 32 + lane];
        float4 vv = ((const float4*)vd1)[lane];
        float s = xv.x * vv.x + xv.y * vv.y + xv.z * vv.z + xv.w * vv.w;
        #pragma unroll
        for (int o = 16; o; o >>= 1) s += __shfl_down_sync(0xffffffffu, s, o);
        if (lane == 0) g_ad1[r] = s;
    } else if (b == 253) {
        for (int i = t; i < NR; i += 256) g_counts[i] = 0;
        if (t == 0) g_done = 0;
    } else if (t < 128) {
        const float *W, *a;
        float* v;
        if (b == 250)      { W = Ws1; a = as1v; v = g_v1; }
        else if (b == 251) { W = Ws2; a = as2v; v = g_v2; }
        else               { W = Wd2; a = ad2v; v = g_vd2; }
        float s = 0.f;
        #pragma unroll 8
        for (int d = 0; d < 128; d++) s += W[t * 128 + d] * a[d];
        v[t] = s;
    }
}

// ---------------- convert + hist + (last block) scan ----------------
#define CONV_BLKS (NO / 8)           // 6250
#define HIST_BLKS 60
#define HIST_CHUNK (NE / HIST_BLKS)  // 10000
__global__ void convert_hist_scan(const float* __restrict__ x, const int* __restrict__ ri) {
    if (blockIdx.x < CONV_BLKS) {
        int row = blockIdx.x * 8 + (threadIdx.x >> 5);
        int lane = threadIdx.x & 31;
        float4 xv = ((const float4*)x)[row * 32 + lane];
        __half2 h01 = __floats2half2_rn(xv.x, xv.y);
        __half2 h23 = __floats2half2_rn(xv.z, xv.w);
        uint2 u;
        *reinterpret_cast<__half2*>(&u.x) = h01;
        *reinterpret_cast<__half2*>(&u.y) = h23;
        reinterpret_cast<uint2*>(g_xh)[row * 32 + lane] = u;
        float4 v1 = ((const float4*)g_v1)[lane];
        float4 v2 = ((const float4*)g_v2)[lane];
        float s1 = xv.x * v1.x + xv.y * v1.y + xv.z * v1.z + xv.w * v1.w;
        float s2 = fmaxf(xv.x, 0.f) * v2.x + fmaxf(xv.y, 0.f) * v2.y +
                   fmaxf(xv.z, 0.f) * v2.z + fmaxf(xv.w, 0.f) * v2.w;
        #pragma unroll
        for (int o = 16; o; o >>= 1) {
            s1 += __shfl_down_sync(0xffffffffu, s1, o);
            s2 += __shfl_down_sync(0xffffffffu, s2, o);
        }
        if (lane == 0) g_as12[row] = make_float2(s1, s2);
        return;
    }
    // ---- histogram blocks ----
    __shared__ int sh[NR];
    int tid = threadIdx.x;
    int b = blockIdx.x - CONV_BLKS;
    int lo = b * HIST_CHUNK, hi = lo + HIST_CHUNK;
    for (int i = tid; i < NR; i += blockDim.x) sh[i] = 0;
    __syncthreads();
    for (int e = lo + tid; e < hi; e += blockDim.x) atomicAdd(&sh[ri[e]], 1);
    __syncthreads();
    for (int i = tid; i < NR; i += blockDim.x)
        if (sh[i]) atomicAdd(&g_counts[i], sh[i]);
    __threadfence();
    __syncthreads();
    __shared__ int s_last;
    if (tid == 0) s_last = (atomicAdd(&g_done, 1) == HIST_BLKS - 1);
    __syncthreads();
    if (!s_last) return;
    // ---- last hist block: exclusive scan of g_counts -> rowptr/cursor ----
    __threadfence();
    int base = tid * 8;
    int local[8];
    int sum = 0;
    #pragma unroll
    for (int k = 0; k < 8; k++) {
        int v = (base + k < NR) ? g_counts[base + k] : 0;
        local[k] = sum;
        sum += v;
    }
    int lane = tid & 31, w = tid >> 5;
    int v = sum;
    #pragma unroll
    for (int o = 1; o < 32; o <<= 1) {
        int n = __shfl_up_sync(0xffffffffu, v, o);
        if (lane >= o) v += n;
    }
    __shared__ int wsum[8];
    if (lane == 31) wsum[w] = v;
    __syncthreads();
    int add = 0;
    for (int i = 0; i < w; i++) add += wsum[i];
    int incl = v + add;
    int excl = incl - sum;
    #pragma unroll
    for (int k = 0; k < 8; k++) {
        int pos = base + k;
        if (pos < NR) {
            int p = excl + local[k];
            g_rowptr[pos] = p;
            g_cursor[pos] = p;
        }
    }
    if (tid == 255) g_rowptr[NR] = incl;
}

// ---------------- scatter: two-phase smem counting ----------------
#define SCAT_BLKS 120
#define SCAT_CHUNK (NE / SCAT_BLKS)  // 5000
__global__ void scatter_kernel(const int* __restrict__ oi, const int* __restrict__ ri) {
    __shared__ int cnt[NR], base[NR];
    int tid = threadIdx.x;  // 512
    int lo = blockIdx.x * SCAT_CHUNK, hi = lo + SCAT_CHUNK;
    for (int i = tid; i < NR; i += 512) cnt[i] = 0;
    __syncthreads();
    for (int e = lo + tid; e < hi; e += 512) atomicAdd(&cnt[ri[e]], 1);
    __syncthreads();
    for (int i = tid; i < NR; i += 512) {
        int c = cnt[i];
        base[i] = c ? atomicAdd(&g_cursor[i], c) : 0;
        cnt[i] = 0;
    }
    __syncthreads();
    for (int e = lo + tid; e < hi; e += 512) {
        int rr = ri[e];
        int pos = base[rr] + atomicAdd(&cnt[rr], 1);
        g_edge[pos] = make_int2(oi[e], e);
    }
}

// ---------------- aggregation: one rider per 256-thread block ----------------
template <int LAYER>
__global__ void __launch_bounds__(256) agg_kernel() {
    int r = blockIdx.x;
    int tid = threadIdx.x, warp = tid >> 5, lane = tid & 31;
    int start = g_rowptr[r], end = g_rowptr[r + 1];
    float adr = (LAYER == 1) ? g_ad1[r] : g_ad2[r];
    const uint2* xh = reinterpret_cast<const uint2*>(g_xh);

    float4 acc = make_float4(0.f, 0.f, 0.f, 0.f);
    float sumw = 0.f;
    for (int j = start + warp * 2; j < end; j += 16) {
        int2 e1 = g_edge[j];
        bool h2 = (j + 1) < end;
        int2 e2 = h2 ? g_edge[j + 1] : e1;
        float2 al1 = g_as12[e1.x];
        float2 al2 = g_as12[e2.x];
        float a1 = (LAYER == 1) ? al1.x : al1.y;
        float a2 = (LAYER == 1) ? al2.x : al2.y;
        uint2 u1 = xh[e1.x * 32 + lane];
        uint2 u2 = xh[e2.x * 32 + lane];
        float w1 = __expf(lrelu(a1 + adr));
        float w2 = h2 ? __expf(lrelu(a2 + adr)) : 0.f;
        float2 f01 = __half22float2(*reinterpret_cast<__half2*>(&u1.x));
        float2 f23 = __half22float2(*reinterpret_cast<__half2*>(&u1.y));
        float2 g01 = __half22float2(*reinterpret_cast<__half2*>(&u2.x));
        float2 g23 = __half22float2(*reinterpret_cast<__half2*>(&u2.y));
        if (LAYER == 2) {
            f01.x = fmaxf(f01.x, 0.f); f01.y = fmaxf(f01.y, 0.f);
            f23.x = fmaxf(f23.x, 0.f); f23.y = fmaxf(f23.y, 0.f);
            g01.x = fmaxf(g01.x, 0.f); g01.y = fmaxf(g01.y, 0.f);
            g23.x = fmaxf(g23.x, 0.f); g23.y = fmaxf(g23.y, 0.f);
        }
        acc.x += w1 * f01.x + w2 * g01.x;
        acc.y += w1 * f01.y + w2 * g01.y;
        acc.z += w1 * f23.x + w2 * g23.x;
        acc.w += w1 * f23.y + w2 * g23.y;
        sumw += w1 + w2;
    }
    __shared__ float4 s_acc[8][32];
    __shared__ float s_w[8];
    s_acc[warp][lane] = acc;
    if (lane == 0) s_w[warp] = sumw;
    __syncthreads();
    if (tid < 128) {
        float tot = s_w[0] + s_w[1] + s_w[2] + s_w[3] + s_w[4] + s_w[5] + s_w[6] + s_w[7];
        const float* sf = reinterpret_cast<const float*>(s_acc);
        float a = 0.f;
        #pragma unroll
        for (int w = 0; w < 8; w++) a += sf[w * 128 + tid];
        g_agg[r * 128 + tid] = a / (tot + 1e-16f);
    }
}

// ---------------- gemm + ad2 epilogue: ad2 = relu(agg@Ws1+b1)·vd2 ----------------
__global__ void gemm_ad2(const float* __restrict__ Ws1, const float* __restrict__ b1) {
    __shared__ float Ws[32 * 128];
    __shared__ float As[16 * 128];
    __shared__ float Os[16 * 128];
    int tid = threadIdx.x;  // 128
    int r0 = blockIdx.x * 16;
    for (int i = tid; i < 16 * 128; i += 128) As[i] = g_agg[r0 * 128 + i];
    float acc[16];
    #pragma unroll
    for (int i = 0; i < 16; i++) acc[i] = 0.f;
    for (int kk = 0; kk < 4; kk++) {
        __syncthreads();
        for (int i = tid; i < 32 * 128; i += 128) Ws[i] = Ws1[kk * 32 * 128 + i];
        __syncthreads();
        #pragma unroll 8
        for (int k = 0; k < 32; k++) {
            float wv = Ws[k * 128 + tid];
            #pragma unroll
            for (int i = 0; i < 16; i++) acc[i] += As[i * 128 + kk * 32 + k] * wv;
        }
    }
    float bv = b1[tid], vt = g_vd2[tid];
    #pragma unroll
    for (int i = 0; i < 16; i++) Os[i * 128 + tid] = fmaxf(acc[i] + bv, 0.f) * vt;
    __syncthreads();
    int warp = tid >> 5, lane = tid & 31;
    for (int i = warp; i < 16; i += 4) {
        float s = Os[i * 128 + lane] + Os[i * 128 + 32 + lane] +
                  Os[i * 128 + 64 + lane] + Os[i * 128 + 96 + lane];
        #pragma unroll
        for (int o = 16; o; o >>= 1) s += __shfl_down_sync(0xffffffffu, s, o);
        if (lane == 0) g_ad2[r0 + i] = s;
    }
}

// ---------------- gemm r2 = agg@Ws2 + b2 ----------------
__global__ void gemm_r2(const float* __restrict__ Ws2, const float* __restrict__ b2) {
    __shared__ float Ws[32 * 128];
    __shared__ float As[16 * 128];
    int tid = threadIdx.x;  // 128
    int r0 = blockIdx.x * 16;
    for (int i = tid; i < 16 * 128; i += 128) As[i] = g_agg[r0 * 128 + i];
    float acc[16];
    #pragma unroll
    for (int i = 0; i < 16; i++) acc[i] = 0.f;
    for (int kk = 0; kk < 4; kk++) {
        __syncthreads();
        for (int i = tid; i < 32 * 128; i += 128) Ws[i] = Ws2[kk * 32 * 128 + i];
        __syncthreads();
        #pragma unroll 8
        for (int k = 0; k < 32; k++) {
            float wv = Ws[k * 128 + tid];
            #pragma unroll
            for (int i = 0; i < 16; i++) acc[i] += As[i * 128 + kk * 32 + k] * wv;
        }
    }
    float bv = b2[tid];
    #pragma unroll
    for (int i = 0; i < 16; i++) g_r2[(r0 + i) * 128 + tid] = acc[i] + bv;
}

// ---------------- scoring: block per rider, r2 row in registers ----------------
__global__ void __launch_bounds__(256) score_kernel(float* __restrict__ out) {
    int r = blockIdx.x;
    int warp = threadIdx.x >> 5, lane = threadIdx.x & 31;
    int start = g_rowptr[r], end = g_rowptr[r + 1];
    float4 rv = ((const float4*)(g_r2 + r * 128))[lane];
    const uint2* xh = reinterpret_cast<const uint2*>(g_xh);
    for (int j = start + warp * 2; j < end; j += 16) {
        int2 e1 = g_edge[j];
        bool h2 = (j + 1) < end;
        int2 e2 = h2 ? g_edge[j + 1] : e1;
        uint2 u1 = xh[e1.x * 32 + lane];
        uint2 u2 = xh[e2.x * 32 + lane];
        float2 f01 = __half22float2(*reinterpret_cast<__half2*>(&u1.x));
        float2 f23 = __half22float2(*reinterpret_cast<__half2*>(&u1.y));
        float2 g01 = __half22float2(*reinterpret_cast<__half2*>(&u2.x));
        float2 g23 = __half22float2(*reinterpret_cast<__half2*>(&u2.y));
        float s1 = fmaxf(f01.x, 0.f) * rv.x + fmaxf(f01.y, 0.f) * rv.y +
                   fmaxf(f23.x, 0.f) * rv.z + fmaxf(f23.y, 0.f) * rv.w;
        float s2 = fmaxf(g01.x, 0.f) * rv.x + fmaxf(g01.y, 0.f) * rv.y +
                   fmaxf(g23.x, 0.f) * rv.z + fmaxf(g23.y, 0.f) * rv.w;
        #pragma unroll
        for (int o = 16; o; o >>= 1) {
            s1 += __shfl_down_sync(0xffffffffu, s1, o);
            s2 += __shfl_down_sync(0xffffffffu, s2, o);
        }
        if (lane == 0) {
            out[e1.y] = 1.f / (1.f + __expf(-s1));
            if (h2) out[e2.y] = 1.f / (1.f + __expf(-s2));
        }
    }
}

// ---------------- launch ----------------
extern "C" void kernel_launch(void* const* d_in, const int* in_sizes, int n_in,
                              void* d_out, int out_size) {
    const float* x_order   = (const float*)d_in[0];
    const float* x_rider   = (const float*)d_in[1];
    const int*   order_idx = (const int*)d_in[2];
    const int*   rider_idx = (const int*)d_in[3];
    const float* Ws1 = (const float*)d_in[4];
    const float* Wd1 = (const float*)d_in[5];
    const float* as1 = (const float*)d_in[6];
    const float* ad1 = (const float*)d_in[7];
    const float* b1  = (const float*)d_in[8];
    const float* Ws2 = (const float*)d_in[9];
    const float* Wd2 = (const float*)d_in[10];
    const float* as2 = (const float*)d_in[11];
    const float* ad2 = (const float*)d_in[12];
    const float* b2  = (const float*)d_in[13];
    float* out = (float*)d_out;

    prep_kernel<<<254, 256>>>(x_rider, Ws1, as1, Wd1, ad1, Ws2, as2, Wd2, ad2);
    convert_hist_scan<<<CONV_BLKS + HIST_BLKS, 256>>>(x_order, rider_idx);
    scatter_kernel<<<SCAT_BLKS, 512>>>(order_idx, rider_idx);
    agg_kernel<1><<<NR, 256>>>();
    gemm_ad2<<<NR / 16, 128>>>(Ws1, b1);
    agg_kernel<2><<<NR, 256>>>();
    gemm_r2<<<NR / 16, 128>>>(Ws2, b2);
    score_kernel<<<NR, 256>>>(out);
}